// round 3
// baseline (speedup 1.0000x reference)
#include <cuda_runtime.h>
#include <cuda_bf16.h>
#include <math.h>

// Problem constants
constexpr int B = 4, S = 2048, E = 1024, H = 16, D = 64;
constexpr int M_ROWS = B * S;   // 8192

// Scratch (device globals: allocation-free rule)
__device__ float g_q[(size_t)B * H * S * D];    // (B,H,S,D)
__device__ float g_k[(size_t)B * H * S * D];
__device__ float g_v[(size_t)B * H * S * D];
__device__ float g_ctx[(size_t)B * S * E];      // (B,S,E) attention context

// ---------------------------------------------------------------------------
// tf32 helpers (3xTF32 split: fp32-level accuracy on tensor cores)
// ---------------------------------------------------------------------------
__device__ __forceinline__ void split_tf32(float x, unsigned& hi, unsigned& lo) {
    unsigned h;
    asm("cvt.rna.tf32.f32 %0, %1;" : "=r"(h) : "f"(x));
    float r = x - __uint_as_float(h);
    unsigned l;
    asm("cvt.rna.tf32.f32 %0, %1;" : "=r"(l) : "f"(r));
    hi = h; lo = l;
}

__device__ __forceinline__ void mma_tf32(float c[4],
                                         const unsigned a[4],
                                         unsigned b0, unsigned b1) {
    asm volatile(
        "mma.sync.aligned.m16n8k8.row.col.f32.tf32.tf32.f32 "
        "{%0,%1,%2,%3}, {%4,%5,%6,%7}, {%8,%9}, {%0,%1,%2,%3};"
        : "+f"(c[0]), "+f"(c[1]), "+f"(c[2]), "+f"(c[3])
        : "r"(a[0]), "r"(a[1]), "r"(a[2]), "r"(a[3]), "r"(b0), "r"(b1));
}

#define CP_ASYNC16(dst_u32, src_ptr) \
    asm volatile("cp.async.cg.shared.global [%0], [%1], 16;\n" :: "r"(dst_u32), "l"(src_ptr) : "memory")
#define CP_COMMIT() asm volatile("cp.async.commit_group;\n" ::: "memory")
#define CP_WAIT0()  asm volatile("cp.async.wait_group 0;\n" ::: "memory")

// ---------------------------------------------------------------------------
// GEMM: C = A(M x E) @ W(E x E) + bias, via 3xTF32 mma.sync (fp32 accuracy).
// CTA tile 128x128, BK=32, 256 threads = 8 warps (2x4), warp tile 64x32.
// MODE 0: C row-major (M x E)
// MODE 1: scatter to head layout (B,H,S,D): row m=(b,s), col n=(h,d)
// ---------------------------------------------------------------------------
constexpr int GBM = 128, GBN = 128, GBK = 32;
constexpr int ASTR = GBK + 4;   // 36 floats  (conflict-free A fragment LDS)
constexpr int BSTR = GBN + 4;   // 132 floats
constexpr int GEMM_SMEM_BYTES = (2 * GBM * ASTR + 2 * GBK * BSTR) * 4;  // 70656

template <int MODE>
__global__ __launch_bounds__(256) void gemm_tf32_kernel(
    const float* __restrict__ A, const float* __restrict__ W,
    const float* __restrict__ bias, float* __restrict__ C)
{
    extern __shared__ float smem[];
    float* As = smem;                      // [2][GBM][ASTR]
    float* Bs = smem + 2 * GBM * ASTR;     // [2][GBK][BSTR]

    const int tid = threadIdx.x;
    const int warpId = tid >> 5, lane = tid & 31;
    const int wm = warpId >> 2, wn = warpId & 3;   // warp grid 2 x 4
    const int gID = lane >> 2, tig = lane & 3;

    const int bx = blockIdx.x, by = blockIdx.y;
    const float* Ag = A + (size_t)(by * GBM) * E;
    const float* Wg = W + bx * GBN;

    float acc[4][4][4];
#pragma unroll
    for (int mt = 0; mt < 4; mt++)
#pragma unroll
        for (int nt = 0; nt < 4; nt++)
#pragma unroll
            for (int r = 0; r < 4; r++) acc[mt][nt][r] = 0.0f;

    const int a_r = tid >> 3;          // 0..31 (+32 per it)
    const int a_c = (tid & 7) * 4;
    const int b_r = tid >> 5;          // 0..7 (+8 per it)
    const int b_c = (tid & 31) * 4;

    auto load_tile = [&](int t, int buf) {
        const float* Asrc = Ag + t * GBK;
        float* Ad = As + buf * GBM * ASTR;
#pragma unroll
        for (int it = 0; it < 4; it++) {
            int r = a_r + it * 32;
            unsigned d = (unsigned)__cvta_generic_to_shared(&Ad[r * ASTR + a_c]);
            CP_ASYNC16(d, Asrc + (size_t)r * E + a_c);
        }
        const float* Bsrc = Wg + (size_t)(t * GBK) * E;
        float* Bd = Bs + buf * GBK * BSTR;
#pragma unroll
        for (int it = 0; it < 4; it++) {
            int r = b_r + it * 8;
            unsigned d = (unsigned)__cvta_generic_to_shared(&Bd[r * BSTR + b_c]);
            CP_ASYNC16(d, Bsrc + (size_t)r * E + b_c);
        }
    };

    constexpr int T = E / GBK;   // 32
    load_tile(0, 0);
    CP_COMMIT();

    for (int t = 0; t < T; t++) {
        const int buf = t & 1;
        CP_WAIT0();
        __syncthreads();
        if (t + 1 < T) {
            load_tile(t + 1, buf ^ 1);
            CP_COMMIT();
        }

        const float* Ab = As + buf * GBM * ASTR + (wm * 64) * ASTR;
        const float* Bb = Bs + buf * GBK * BSTR + wn * 32;

#pragma unroll
        for (int k8 = 0; k8 < 4; k8++) {
            const int kb = k8 * 8;
            unsigned ah[4][4], al[4][4];
#pragma unroll
            for (int mt = 0; mt < 4; mt++) {
                const int r0 = mt * 16 + gID;
                split_tf32(Ab[(r0    ) * ASTR + kb + tig    ], ah[mt][0], al[mt][0]);
                split_tf32(Ab[(r0 + 8) * ASTR + kb + tig    ], ah[mt][1], al[mt][1]);
                split_tf32(Ab[(r0    ) * ASTR + kb + tig + 4], ah[mt][2], al[mt][2]);
                split_tf32(Ab[(r0 + 8) * ASTR + kb + tig + 4], ah[mt][3], al[mt][3]);
            }
            unsigned bh[4][2], bl[4][2];
#pragma unroll
            for (int nt = 0; nt < 4; nt++) {
                const int n0 = nt * 8 + gID;
                split_tf32(Bb[(kb + tig    ) * BSTR + n0], bh[nt][0], bl[nt][0]);
                split_tf32(Bb[(kb + tig + 4) * BSTR + n0], bh[nt][1], bl[nt][1]);
            }
#pragma unroll
            for (int mt = 0; mt < 4; mt++)
#pragma unroll
                for (int nt = 0; nt < 4; nt++) {
                    mma_tf32(acc[mt][nt], ah[mt], bh[nt][0], bh[nt][1]);   // hi*hi
                    mma_tf32(acc[mt][nt], ah[mt], bl[nt][0], bl[nt][1]);   // hi*lo
                    mma_tf32(acc[mt][nt], al[mt], bh[nt][0], bh[nt][1]);   // lo*hi
                }
        }
        __syncthreads();
    }

    // Epilogue: bias + store
#pragma unroll
    for (int mt = 0; mt < 4; mt++) {
        const int r0 = by * GBM + wm * 64 + mt * 16 + gID;
#pragma unroll
        for (int nt = 0; nt < 4; nt++) {
            const int c0 = bx * GBN + wn * 32 + nt * 8 + tig * 2;
            const float v00 = acc[mt][nt][0] + bias[c0];
            const float v01 = acc[mt][nt][1] + bias[c0 + 1];
            const float v10 = acc[mt][nt][2] + bias[c0];
            const float v11 = acc[mt][nt][3] + bias[c0 + 1];
            if (MODE == 0) {
                C[(size_t)r0 * E + c0]           = v00;
                C[(size_t)r0 * E + c0 + 1]       = v01;
                C[(size_t)(r0 + 8) * E + c0]     = v10;
                C[(size_t)(r0 + 8) * E + c0 + 1] = v11;
            } else {
                const int h = c0 / D, d = c0 % D;
                {
                    const int b = r0 / S, s = r0 % S;
                    C[((((size_t)b * H + h) * S) + s) * D + d]     = v00;
                    C[((((size_t)b * H + h) * S) + s) * D + d + 1] = v01;
                }
                {
                    const int b = (r0 + 8) / S, s = (r0 + 8) % S;
                    C[((((size_t)b * H + h) * S) + s) * D + d]     = v10;
                    C[((((size_t)b * H + h) * S) + s) * D + d + 1] = v11;
                }
            }
        }
    }
}

// ---------------------------------------------------------------------------
// Causal flash attention, Br=Bc=64, D=64, 3xTF32 mma for QK^T and PV.
// 256 threads. mma warp grid 2x4 (warp tile: S 32q x 16key, O 32q x 16d).
// Softmax: scalar 16x16 thread grid (4 rows x 4 cols each), unchanged logic.
// smem stride 68 => fragment LDS bank = (4*gID + tig) mod 32, conflict-free.
// ---------------------------------------------------------------------------
constexpr int AST = 68;
constexpr int ATT_BUF = 64 * AST;                       // floats per buffer
constexpr int ATT_SMEM_BYTES = (4 * ATT_BUF + 128) * 4; // Q,K,V,P + corr/linv

__global__ __launch_bounds__(256) void flash_attn_kernel(
    const float* __restrict__ Qg, const float* __restrict__ Kg,
    const float* __restrict__ Vg, float* __restrict__ ctx)
{
    extern __shared__ float sm[];
    float* Qs = sm;
    float* Ks = sm + ATT_BUF;
    float* Vs = sm + 2 * ATT_BUF;
    float* Ps = sm + 3 * ATT_BUF;
    float* corr_s = sm + 4 * ATT_BUF;        // [64]
    float* linv_s = corr_s + 64;             // [64]

    const int tid = threadIdx.x;
    const int tx = tid % 16, ty = tid / 16;          // scalar-phase mapping
    const int warpId = tid >> 5, lane = tid & 31;    // mma-phase mapping
    const int wm = warpId >> 2, wn = warpId & 3;     // 2 x 4 warp grid
    const int gID = lane >> 2, tig = lane & 3;

    const int qt = blockIdx.x;
    const int bh = blockIdx.y;
    const int b = bh / H, h = bh % H;

    const float* Qb = Qg + (size_t)bh * S * D;
    const float* Kb = Kg + (size_t)bh * S * D;
    const float* Vb = Vg + (size_t)bh * S * D;

    // Load Q tile, pre-scaled by 1/sqrt(64)=0.125 (power of two: exact)
#pragma unroll
    for (int it = 0; it < 4; it++) {
        const int idx = tid + it * 256;
        const int r = idx >> 4;
        const int c = (idx & 15) * 4;
        float4 v = *(const float4*)(Qb + (size_t)(qt * 64 + r) * D + c);
        Qs[r * AST + c]     = v.x * 0.125f;
        Qs[r * AST + c + 1] = v.y * 0.125f;
        Qs[r * AST + c + 2] = v.z * 0.125f;
        Qs[r * AST + c + 3] = v.w * 0.125f;
    }

    // Per-thread softmax state (rows ty*4..ty*4+3)
    float m_i[4], l_i[4];
#pragma unroll
    for (int i = 0; i < 4; i++) { m_i[i] = -1e30f; l_i[i] = 0.0f; }

    // O accumulators: warp tile 32q x 16d; frags [mt][nt]
    float oacc[2][2][4];
#pragma unroll
    for (int mt = 0; mt < 2; mt++)
#pragma unroll
        for (int nt = 0; nt < 2; nt++)
#pragma unroll
            for (int r = 0; r < 4; r++) oacc[mt][nt][r] = 0.0f;

    for (int kt = 0; kt <= qt; kt++) {
        __syncthreads();   // prev iter done with Ks/Vs/Ps; Qs visible (iter 0)
#pragma unroll
        for (int it = 0; it < 4; it++) {
            const int idx = tid + it * 256;
            const int r = idx >> 4;
            const int c = (idx & 15) * 4;
            float4 kv = *(const float4*)(Kb + (size_t)(kt * 64 + r) * D + c);
            *(float4*)&Ks[r * AST + c] = kv;
            float4 vv = *(const float4*)(Vb + (size_t)(kt * 64 + r) * D + c);
            *(float4*)&Vs[r * AST + c] = vv;
        }
        __syncthreads();

        // ---- S = (Q*scale) @ K^T via 3xTF32 mma ----
        {
            float sacc[2][2][4];
#pragma unroll
            for (int mt = 0; mt < 2; mt++)
#pragma unroll
                for (int nt = 0; nt < 2; nt++)
#pragma unroll
                    for (int r = 0; r < 4; r++) sacc[mt][nt][r] = 0.0f;

#pragma unroll
            for (int k8 = 0; k8 < 8; k8++) {
                const int kb = k8 * 8;
                unsigned ah[2][4], al[2][4];
#pragma unroll
                for (int mt = 0; mt < 2; mt++) {
                    const int r0 = wm * 32 + mt * 16 + gID;
                    split_tf32(Qs[(r0    ) * AST + kb + tig    ], ah[mt][0], al[mt][0]);
                    split_tf32(Qs[(r0 + 8) * AST + kb + tig    ], ah[mt][1], al[mt][1]);
                    split_tf32(Qs[(r0    ) * AST + kb + tig + 4], ah[mt][2], al[mt][2]);
                    split_tf32(Qs[(r0 + 8) * AST + kb + tig + 4], ah[mt][3], al[mt][3]);
                }
                unsigned bhf[2][2], blf[2][2];
#pragma unroll
                for (int nt = 0; nt < 2; nt++) {
                    const int n0 = wn * 16 + nt * 8 + gID;   // key index
                    split_tf32(Ks[n0 * AST + kb + tig    ], bhf[nt][0], blf[nt][0]);
                    split_tf32(Ks[n0 * AST + kb + tig + 4], bhf[nt][1], blf[nt][1]);
                }
#pragma unroll
                for (int mt = 0; mt < 2; mt++)
#pragma unroll
                    for (int nt = 0; nt < 2; nt++) {
                        mma_tf32(sacc[mt][nt], ah[mt], bhf[nt][0], bhf[nt][1]);
                        mma_tf32(sacc[mt][nt], ah[mt], blf[nt][0], blf[nt][1]);
                        mma_tf32(sacc[mt][nt], al[mt], bhf[nt][0], bhf[nt][1]);
                    }
            }
            // write S fragments to Ps
#pragma unroll
            for (int mt = 0; mt < 2; mt++) {
                const int r0 = wm * 32 + mt * 16 + gID;
#pragma unroll
                for (int nt = 0; nt < 2; nt++) {
                    const int c0 = wn * 16 + nt * 8 + tig * 2;
                    Ps[r0 * AST + c0]           = sacc[mt][nt][0];
                    Ps[r0 * AST + c0 + 1]       = sacc[mt][nt][1];
                    Ps[(r0 + 8) * AST + c0]     = sacc[mt][nt][2];
                    Ps[(r0 + 8) * AST + c0 + 1] = sacc[mt][nt][3];
                }
            }
        }
        __syncthreads();

        // ---- scalar online softmax (rows ty*4+i, cols tx*4+j) ----
        const bool diag = (kt == qt);
#pragma unroll
        for (int i = 0; i < 4; i++) {
            const int row = ty * 4 + i;
            float sv[4];
#pragma unroll
            for (int j = 0; j < 4; j++) {
                float s = Ps[row * AST + tx * 4 + j];
                if (diag && (tx * 4 + j) > row) s = -1e30f;
                sv[j] = s;
            }
            float rmax = fmaxf(fmaxf(sv[0], sv[1]), fmaxf(sv[2], sv[3]));
#pragma unroll
            for (int off = 8; off >= 1; off >>= 1)
                rmax = fmaxf(rmax, __shfl_xor_sync(0xffffffffu, rmax, off));
            const float m_new = fmaxf(m_i[i], rmax);
            const float corr = __expf(m_i[i] - m_new);
            float rsum = 0.0f;
#pragma unroll
            for (int j = 0; j < 4; j++) {
                const float p = __expf(sv[j] - m_new);
                Ps[row * AST + tx * 4 + j] = p;
                rsum += p;
            }
#pragma unroll
            for (int off = 8; off >= 1; off >>= 1)
                rsum += __shfl_xor_sync(0xffffffffu, rsum, off);
            l_i[i] = l_i[i] * corr + rsum;
            m_i[i] = m_new;
            if (tx == 0) corr_s[row] = corr;
        }
        __syncthreads();

        // ---- O = O*corr + P @ V via 3xTF32 mma ----
#pragma unroll
        for (int mt = 0; mt < 2; mt++) {
            const int r0 = wm * 32 + mt * 16 + gID;
            const float cl = corr_s[r0];
            const float ch = corr_s[r0 + 8];
#pragma unroll
            for (int nt = 0; nt < 2; nt++) {
                oacc[mt][nt][0] *= cl; oacc[mt][nt][1] *= cl;
                oacc[mt][nt][2] *= ch; oacc[mt][nt][3] *= ch;
            }
        }
#pragma unroll
        for (int k8 = 0; k8 < 8; k8++) {
            const int kb = k8 * 8;                      // key-dim chunk
            unsigned ah[2][4], al[2][4];
#pragma unroll
            for (int mt = 0; mt < 2; mt++) {
                const int r0 = wm * 32 + mt * 16 + gID;
                split_tf32(Ps[(r0    ) * AST + kb + tig    ], ah[mt][0], al[mt][0]);
                split_tf32(Ps[(r0 + 8) * AST + kb + tig    ], ah[mt][1], al[mt][1]);
                split_tf32(Ps[(r0    ) * AST + kb + tig + 4], ah[mt][2], al[mt][2]);
                split_tf32(Ps[(r0 + 8) * AST + kb + tig + 4], ah[mt][3], al[mt][3]);
            }
            unsigned bhf[2][2], blf[2][2];
#pragma unroll
            for (int nt = 0; nt < 2; nt++) {
                const int n0 = wn * 16 + nt * 8 + gID;   // d index
                split_tf32(Vs[(kb + tig    ) * AST + n0], bhf[nt][0], blf[nt][0]);
                split_tf32(Vs[(kb + tig + 4) * AST + n0], bhf[nt][1], blf[nt][1]);
            }
#pragma unroll
            for (int mt = 0; mt < 2; mt++)
#pragma unroll
                for (int nt = 0; nt < 2; nt++) {
                    mma_tf32(oacc[mt][nt], ah[mt], bhf[nt][0], bhf[nt][1]);
                    mma_tf32(oacc[mt][nt], ah[mt], blf[nt][0], blf[nt][1]);
                    mma_tf32(oacc[mt][nt], al[mt], bhf[nt][0], bhf[nt][1]);
                }
        }
    }

    // publish 1/l per row (l_i uniform across the 16 lanes of a row group)
#pragma unroll
    for (int i = 0; i < 4; i++) {
        if (tx == 0) linv_s[ty * 4 + i] = 1.0f / l_i[i];
    }
    __syncthreads();

    // write O: row r -> ctx[(b, qt*64+r), h*64 + c]
#pragma unroll
    for (int mt = 0; mt < 2; mt++) {
        const int r0 = wm * 32 + mt * 16 + gID;
        const float il = linv_s[r0];
        const float ih = linv_s[r0 + 8];
#pragma unroll
        for (int nt = 0; nt < 2; nt++) {
            const int c0 = wn * 16 + nt * 8 + tig * 2;
            float* p0 = &ctx[((size_t)b * S + qt * 64 + r0) * E + h * D + c0];
            float* p1 = &ctx[((size_t)b * S + qt * 64 + r0 + 8) * E + h * D + c0];
            p0[0] = oacc[mt][nt][0] * il;
            p0[1] = oacc[mt][nt][1] * il;
            p1[0] = oacc[mt][nt][2] * ih;
            p1[1] = oacc[mt][nt][3] * ih;
        }
    }
}

// ---------------------------------------------------------------------------
extern "C" void kernel_launch(void* const* d_in, const int* in_sizes, int n_in,
                              void* d_out, int out_size)
{
    const float* x  = (const float*)d_in[0];
    const float* Wq = (const float*)d_in[1];
    const float* bq = (const float*)d_in[2];
    const float* Wk = (const float*)d_in[3];
    const float* bk = (const float*)d_in[4];
    const float* Wv = (const float*)d_in[5];
    const float* bv = (const float*)d_in[6];
    const float* Wo = (const float*)d_in[7];
    const float* bo = (const float*)d_in[8];
    float* out = (float*)d_out;

    float *q, *k, *v, *ctx;
    cudaGetSymbolAddress((void**)&q,   g_q);
    cudaGetSymbolAddress((void**)&k,   g_k);
    cudaGetSymbolAddress((void**)&v,   g_v);
    cudaGetSymbolAddress((void**)&ctx, g_ctx);

    cudaFuncSetAttribute(gemm_tf32_kernel<0>,
                         cudaFuncAttributeMaxDynamicSharedMemorySize, GEMM_SMEM_BYTES);
    cudaFuncSetAttribute(gemm_tf32_kernel<1>,
                         cudaFuncAttributeMaxDynamicSharedMemorySize, GEMM_SMEM_BYTES);
    cudaFuncSetAttribute(flash_attn_kernel,
                         cudaFuncAttributeMaxDynamicSharedMemorySize, ATT_SMEM_BYTES);

    dim3 gemm_grid(E / GBN, M_ROWS / GBM);   // (8, 64)
    gemm_tf32_kernel<1><<<gemm_grid, 256, GEMM_SMEM_BYTES>>>(x, Wq, bq, q);
    gemm_tf32_kernel<1><<<gemm_grid, 256, GEMM_SMEM_BYTES>>>(x, Wk, bk, k);
    gemm_tf32_kernel<1><<<gemm_grid, 256, GEMM_SMEM_BYTES>>>(x, Wv, bv, v);

    dim3 attn_grid(S / 64, B * H);           // (32, 64)
    flash_attn_kernel<<<attn_grid, 256, ATT_SMEM_BYTES>>>(q, k, v, ctx);

    gemm_tf32_kernel<0><<<gemm_grid, 256, GEMM_SMEM_BYTES>>>(ctx, Wo, bo, out);
}